// round 10
// baseline (speedup 1.0000x reference)
#include <cuda_runtime.h>
#include <cstdint>

// Problem dims
#define BB   32
#define SS   256
#define EE   256
#define HH   256
#define G4   1024   // 4*H
#define HD2  512    // 2*H
#define LLAB 9
#define SBN  8192   // B*S
#define NPART 64    // CTAs per direction in recurrent kernel (H/NPART = 4 j per CTA)

// ---------------- scratch (static device allocations only) ----------------
static __device__ float g_xp0[(size_t)G4 * SBN];           // dir-f input proj [g][sb]
static __device__ float g_xp1[(size_t)G4 * SBN];           // dir-r input proj [g][sb]
static __device__ float g_out0[(size_t)SBN * HD2];         // layer0 output [sb][512]
static __device__ float g_out1[(size_t)SBN * HD2];         // layer1 output [sb][512]
static __device__ float g_h[2][2][HH * BB];                // [buf][dir][k][b]
static __device__ float g_em[(size_t)SBN * LLAB];          // emissions [sb][9]
static __device__ float g_partial[BB];
static __device__ unsigned g_barcnt[2];
static __device__ unsigned g_bargen[2];

// ---------------- helpers ----------------
__device__ __forceinline__ float sigmf(float x) {
    return 1.f / (1.f + __expf(-x));
}

// Per-direction sense-reversing grid barrier (all CTAs of that dir co-resident).
__device__ __forceinline__ void grid_barrier(int d, unsigned nb) {
    __threadfence();          // make this thread's global writes visible
    __syncthreads();          // everyone in CTA done writing
    if (threadIdx.x == 0) {
        unsigned gen = *((volatile unsigned*)&g_bargen[d]);
        if (atomicAdd(&g_barcnt[d], 1u) == nb - 1u) {
            g_barcnt[d] = 0u;
            __threadfence();
            atomicAdd(&g_bargen[d], 1u);  // release
        } else {
            while (*((volatile unsigned*)&g_bargen[d]) == gen) { }
        }
        __threadfence();
    }
    __syncthreads();
}

// ---------------- kernel 1: C[m][n] = A[m][:K] . B[n][:K] + bias[m] ----------------
// A: [M][K] row-major (weights), B: [N][K] row-major (activations), C: [M][N] row-major.
// 64x64 tile, BK=16, 256 threads, 4x4 register tile, register-prefetch pipeline.
// gridDim.z selects the (A,bias,C) set so fwd+rev projections run in ONE launch.
// If ids != nullptr, B row sb is gathered from emb[ids[b*SS+t]] (sb = t*32+b),
// fusing the embedding lookup into the layer-0 GEMM.
__global__ void gemm_nt2(const float* __restrict__ A0, const float* __restrict__ bias0,
                         float* __restrict__ C0,
                         const float* __restrict__ A1, const float* __restrict__ bias1,
                         float* __restrict__ C1,
                         const float* __restrict__ Bm, const int* __restrict__ ids,
                         int N, int K) {
    const float* A    = blockIdx.z ? A1 : A0;
    const float* bias = blockIdx.z ? bias1 : bias0;
    float*       C    = blockIdx.z ? C1 : C0;

    __shared__ __align__(16) float As[16][64];
    __shared__ __align__(16) float Bs[16][64];
    const int tid = threadIdx.x;
    const int tx = tid & 15, ty = tid >> 4;
    const int m0 = blockIdx.y * 64, n0 = blockIdx.x * 64;
    const int lr = tid >> 2;            // 0..63
    const int lk = (tid & 3) * 4;       // 0,4,8,12
    float acc[4][4] = {};
    const float* Ap = A + (size_t)(m0 + lr) * K + lk;
    int brow = n0 + lr;
    const float* Bp;
    if (ids) {
        int t = brow >> 5, b = brow & 31;
        int tok = ids[b * SS + t];
        Bp = Bm + (size_t)tok * K + lk;    // Bm = emb
    } else {
        Bp = Bm + (size_t)brow * K + lk;
    }

    // prologue load
    float4 a4 = *(const float4*)(Ap);
    float4 b4 = *(const float4*)(Bp);

    for (int k0 = 0; k0 < K; k0 += 16) {
        As[lk + 0][lr] = a4.x; As[lk + 1][lr] = a4.y;
        As[lk + 2][lr] = a4.z; As[lk + 3][lr] = a4.w;
        Bs[lk + 0][lr] = b4.x; Bs[lk + 1][lr] = b4.y;
        Bs[lk + 2][lr] = b4.z; Bs[lk + 3][lr] = b4.w;
        __syncthreads();
        // prefetch next tile while this tile computes
        if (k0 + 16 < K) {
            a4 = *(const float4*)(Ap + k0 + 16);
            b4 = *(const float4*)(Bp + k0 + 16);
        }
#pragma unroll
        for (int kk = 0; kk < 16; ++kk) {
            float4 av = *(const float4*)&As[kk][ty * 4];
            float4 bv = *(const float4*)&Bs[kk][tx * 4];
            acc[0][0] = fmaf(av.x, bv.x, acc[0][0]);
            acc[0][1] = fmaf(av.x, bv.y, acc[0][1]);
            acc[0][2] = fmaf(av.x, bv.z, acc[0][2]);
            acc[0][3] = fmaf(av.x, bv.w, acc[0][3]);
            acc[1][0] = fmaf(av.y, bv.x, acc[1][0]);
            acc[1][1] = fmaf(av.y, bv.y, acc[1][1]);
            acc[1][2] = fmaf(av.y, bv.z, acc[1][2]);
            acc[1][3] = fmaf(av.y, bv.w, acc[1][3]);
            acc[2][0] = fmaf(av.z, bv.x, acc[2][0]);
            acc[2][1] = fmaf(av.z, bv.y, acc[2][1]);
            acc[2][2] = fmaf(av.z, bv.z, acc[2][2]);
            acc[2][3] = fmaf(av.z, bv.w, acc[2][3]);
            acc[3][0] = fmaf(av.w, bv.x, acc[3][0]);
            acc[3][1] = fmaf(av.w, bv.y, acc[3][1]);
            acc[3][2] = fmaf(av.w, bv.z, acc[3][2]);
            acc[3][3] = fmaf(av.w, bv.w, acc[3][3]);
        }
        __syncthreads();
    }
#pragma unroll
    for (int i = 0; i < 4; ++i) {
        int m = m0 + ty * 4 + i;
        float bb = bias[m];
        float4 o = make_float4(acc[i][0] + bb, acc[i][1] + bb,
                               acc[i][2] + bb, acc[i][3] + bb);
        *(float4*)&C[(size_t)m * N + n0 + tx * 4] = o;
    }
}

// ---------------- kernel 2: persistent BiLSTM layer ----------------
// grid = 2*NPART blocks, 256 threads. blockIdx>>6 = dir, &63 = part.
// Each CTA: h indices j0..j0+3, gate rows {q*256 + j0+jj}, q=0..3 (i,f,g,o).
// Thread = (r = gate row 0..15, col = batch quad 0..7, ks = k-half 0..1):
// per k-step 1 LDS(w) + 1 LDS.128(h) + 4 FFMA.
// Dynamic smem layout (floats):
//   w   [256][16]   @ 0      (16 KB)
//   h   [256][32]   @ 4096   (32 KB)
//   g   [16][32]    @ 12288
//   part[16][32]    @ 12800
//   c   [4][32]     @ 13312
#define LSTM_SMEM_FLOATS (4096 + 8192 + 512 + 512 + 128)
__global__ void lstm_layer(const float* __restrict__ xpf, const float* __restrict__ xpr,
                           const float* __restrict__ whhf, const float* __restrict__ whhr,
                           float* __restrict__ out) {
    extern __shared__ __align__(16) float sm[];
    float* sh_w = sm;            // [k][r]
    float* sh_h = sm + 4096;     // [k][b]
    float* sh_g = sm + 12288;    // [r][b]
    float* sh_p = sm + 12800;    // [r][b]
    float* sh_c = sm + 13312;    // [jj][b]

    const int tid  = threadIdx.x;
    const int dir  = blockIdx.x >> 6;
    const int part = blockIdx.x & 63;
    const int j0   = part * 4;
    const float* xp  = dir ? xpr : xpf;
    const float* whh = dir ? whhr : whhf;

    // load weight slice once: 16 rows x 256 k, stored [k][r]
    for (int idx = tid; idx < 16 * 256; idx += 256) {
        int r = idx >> 8, k = idx & 255;
        int q = r >> 2, jj = r & 3;
        sh_w[k * 16 + r] = whh[(size_t)(q * 256 + j0 + jj) * 256 + k];
    }
    if (tid < 128) {
        int jj = tid >> 5, bb = tid & 31;
        sh_c[jj * 32 + bb] = 0.f;
    }

    const int col = tid & 7;            // batch quad: b = col*4 .. col*4+3
    const int r   = (tid >> 3) & 15;    // gate row 0..15 = (q<<2)|jj
    const int ks  = tid >> 7;           // k half
    const int q   = r >> 2, jjr = r & 3;
    const int grow = q * 256 + j0 + jjr;
    const float* xpbase = xp + (size_t)grow * SBN;
    const float* wbase = sh_w + ks * 128 * 16 + r;
    const float* hbase = sh_h + ks * 128 * 32 + col * 4;
    __syncthreads();                    // sh_w / sh_c ready (CTA-local)

    int cur = 0;
    for (int step = 0; step < SS; ++step) {
        int t = dir ? (SS - 1 - step) : step;

        float acc0, acc1, acc2, acc3;
        if (ks == 0) {
            float4 xv = *(const float4*)&xpbase[t * 32 + col * 4];
            acc0 = xv.x; acc1 = xv.y; acc2 = xv.z; acc3 = xv.w;
        } else {
            acc0 = acc1 = acc2 = acc3 = 0.f;
        }

        if (step > 0) {   // step 0: h == 0, gates = input projection only
            // stage full h vector (bypass L1: written by other SMs within launch)
            {
                const float4* src = (const float4*)(g_h[cur][dir]);
                float4* dst = (float4*)sh_h;
#pragma unroll
                for (int i = 0; i < 8; ++i) dst[tid + i * 256] = __ldcg(&src[tid + i * 256]);
            }
            __syncthreads();

#pragma unroll 8
            for (int kk = 0; kk < 128; ++kk) {
                float w0 = wbase[kk * 16];
                float4 hv = *(const float4*)(hbase + kk * 32);
                acc0 = fmaf(w0, hv.x, acc0);
                acc1 = fmaf(w0, hv.y, acc1);
                acc2 = fmaf(w0, hv.z, acc2);
                acc3 = fmaf(w0, hv.w, acc3);
            }
        }
        if (ks == 1)
            *(float4*)&sh_p[r * 32 + col * 4] = make_float4(acc0, acc1, acc2, acc3);
        __syncthreads();
        if (ks == 0) {
            float4 pv = *(const float4*)&sh_p[r * 32 + col * 4];
            *(float4*)&sh_g[r * 32 + col * 4] =
                make_float4(acc0 + pv.x, acc1 + pv.y, acc2 + pv.z, acc3 + pv.w);
        }
        __syncthreads();
        if (tid < 128) {
            int jj = tid >> 5, bb = tid & 31;
            float gi = sh_g[(0 * 4 + jj) * 32 + bb];
            float gf = sh_g[(1 * 4 + jj) * 32 + bb];
            float gg = sh_g[(2 * 4 + jj) * 32 + bb];
            float go = sh_g[(3 * 4 + jj) * 32 + bb];
            float c = sh_c[jj * 32 + bb];
            c = sigmf(gf) * c + sigmf(gi) * tanhf(gg);   // accurate tanh: 256 sequential steps
            float h = sigmf(go) * tanhf(c);
            sh_c[jj * 32 + bb] = c;
            __stcg(&g_h[cur ^ 1][dir][(j0 + jj) * 32 + bb], h);
            out[((size_t)t * 32 + bb) * HD2 + dir * 256 + j0 + jj] = h;
        }
        grid_barrier(dir, NPART);
        cur ^= 1;
    }
}

// ---------------- kernel 3: emissions ----------------
// em[sb][l] = out1[sb][:512] . w_out[l][:512] + b_out[l]; one warp per sb row.
__global__ void emis_kernel(const float* __restrict__ x, const float* __restrict__ w,
                            const float* __restrict__ bo) {
    int row  = blockIdx.x * 8 + (threadIdx.x >> 5);
    int lane = threadIdx.x & 31;
    const float* xr = x + (size_t)row * HD2;
    float a[LLAB] = {};
#pragma unroll
    for (int i = 0; i < 16; ++i) {
        float xv = xr[i * 32 + lane];
#pragma unroll
        for (int l = 0; l < LLAB; ++l)
            a[l] = fmaf(xv, w[l * HD2 + i * 32 + lane], a[l]);
    }
#pragma unroll
    for (int off = 16; off > 0; off >>= 1) {
#pragma unroll
        for (int l = 0; l < LLAB; ++l)
            a[l] += __shfl_xor_sync(0xffffffffu, a[l], off);
    }
    if (lane < LLAB) g_em[(size_t)row * LLAB + lane] = a[lane] + bo[lane];
}

// ---------------- kernel 4: CRF (one block per batch, one warp) ----------------
__global__ void crf_kernel(const int* __restrict__ labels, const int* __restrict__ mask,
                           const float* __restrict__ start, const float* __restrict__ end_,
                           const float* __restrict__ trans) {
    __shared__ float em_s[SS][LLAB];
    __shared__ float tr_s[81], st_s[LLAB], en_s[LLAB];
    __shared__ int   tg_s[SS];
    __shared__ float mk_s[SS];
    __shared__ float sh_al[LLAB];
    const int b = blockIdx.x, tid = threadIdx.x;

    for (int i = tid; i < SS * LLAB; i += 32) {
        int t = i / LLAB, l = i - t * LLAB;
        em_s[t][l] = g_em[((size_t)t * 32 + b) * LLAB + l];
    }
    for (int i = tid; i < 81; i += 32) tr_s[i] = trans[i];
    if (tid < LLAB) { st_s[tid] = start[tid]; en_s[tid] = end_[tid]; }
    for (int i = tid; i < SS; i += 32) {
        tg_s[i] = labels[b * SS + i];
        mk_s[i] = (float)mask[b * SS + i];
    }
    __syncwarp();

    const int j = tid;
    float a = (j < LLAB) ? st_s[j] + em_s[0][j] : 0.f;
    for (int t = 1; t < SS; ++t) {
        if (j < LLAB) sh_al[j] = a;
        __syncwarp();
        if (j < LLAB) {
            float m = -1e30f;
#pragma unroll
            for (int i = 0; i < LLAB; ++i) m = fmaxf(m, sh_al[i] + tr_s[i * LLAB + j]);
            float s = 0.f;
#pragma unroll
            for (int i = 0; i < LLAB; ++i) s += __expf(sh_al[i] + tr_s[i * LLAB + j] - m);
            float nxt = m + __logf(s) + em_s[t][j];
            if (mk_s[t] > 0.f) a = nxt;
        }
        __syncwarp();
    }
    if (j < LLAB) sh_al[j] = a;
    __syncwarp();
    if (tid == 0) {
        float m = -1e30f;
#pragma unroll
        for (int i = 0; i < LLAB; ++i) m = fmaxf(m, sh_al[i] + en_s[i]);
        float s = 0.f;
#pragma unroll
        for (int i = 0; i < LLAB; ++i) s += __expf(sh_al[i] + en_s[i] - m);
        float den = m + __logf(s);
        int prev = tg_s[0];
        float sc = st_s[prev] + em_s[0][prev];
        for (int t = 1; t < SS; ++t) {
            int tt = tg_s[t];
            float mm = mk_s[t];
            sc += (tr_s[prev * LLAB + tt] + em_s[t][tt]) * mm;
            if (mm > 0.f) prev = tt;
        }
        sc += en_s[prev];
        g_partial[b] = den - sc;   // = -(num - den)
    }
}

__global__ void final_sum(float* __restrict__ out) {
    float s = 0.f;
#pragma unroll
    for (int i = 0; i < BB; ++i) s += g_partial[i];
    out[0] = s;
}

// ---------------- launch ----------------
extern "C" void kernel_launch(void* const* d_in, const int* in_sizes, int n_in,
                              void* d_out, int out_size) {
    (void)in_sizes; (void)n_in; (void)out_size;
    const int*   ids    = (const int*)d_in[0];
    const int*   amask  = (const int*)d_in[1];
    const int*   labels = (const int*)d_in[2];
    const float* emb    = (const float*)d_in[3];
    const float* wih0f  = (const float*)d_in[4];
    const float* whh0f  = (const float*)d_in[5];
    const float* b0f    = (const float*)d_in[6];
    const float* wih0r  = (const float*)d_in[7];
    const float* whh0r  = (const float*)d_in[8];
    const float* b0r    = (const float*)d_in[9];
    const float* wih1f  = (const float*)d_in[10];
    const float* whh1f  = (const float*)d_in[11];
    const float* b1f    = (const float*)d_in[12];
    const float* wih1r  = (const float*)d_in[13];
    const float* whh1r  = (const float*)d_in[14];
    const float* b1r    = (const float*)d_in[15];
    const float* w_out  = (const float*)d_in[16];
    const float* b_out  = (const float*)d_in[17];
    const float* start_t = (const float*)d_in[18];
    const float* end_t   = (const float*)d_in[19];
    const float* trans   = (const float*)d_in[20];

    float* xp0; cudaGetSymbolAddress((void**)&xp0, g_xp0);
    float* xp1; cudaGetSymbolAddress((void**)&xp1, g_xp1);
    float* out0; cudaGetSymbolAddress((void**)&out0, g_out0);
    float* out1; cudaGetSymbolAddress((void**)&out1, g_out1);

    const int lstm_smem = LSTM_SMEM_FLOATS * 4;   // 53760 B
    cudaFuncSetAttribute(lstm_layer, cudaFuncAttributeMaxDynamicSharedMemorySize, lstm_smem);

    dim3 pgrid(SBN / 64, G4 / 64, 2), pblk(256);
    // layer 0 input projection, embedding gather fused via ids
    gemm_nt2<<<pgrid, pblk>>>(wih0f, b0f, xp0, wih0r, b0r, xp1, emb, ids, SBN, EE);

    lstm_layer<<<2 * NPART, 256, lstm_smem>>>(xp0, xp1, whh0f, whh0r, out0);

    gemm_nt2<<<pgrid, pblk>>>(wih1f, b1f, xp0, wih1r, b1r, xp1, out0, nullptr, SBN, HD2);

    lstm_layer<<<2 * NPART, 256, lstm_smem>>>(xp0, xp1, whh1f, whh1r, out1);

    emis_kernel<<<SBN / 8, 256>>>(out1, w_out, b_out);
    crf_kernel<<<BB, 32>>>(labels, amask, start_t, end_t, trans);
    final_sum<<<1, 1>>>((float*)d_out);
}

// round 11
// speedup vs baseline: 1.1767x; 1.1767x over previous
#include <cuda_runtime.h>
#include <cstdint>

// Problem dims
#define BB   32
#define SS   256
#define EE   256
#define HH   256
#define G4   1024   // 4*H
#define HD2  512    // 2*H
#define LLAB 9
#define SBN  8192   // B*S
#define NGRP 8      // batch groups per direction (4 batches each)
#define NCPG 8      // CTAs per group (32 h-units each)

// ---------------- scratch (static device allocations only) ----------------
static __device__ float g_xp0[(size_t)G4 * SBN];           // dir-f input proj [g][sb]
static __device__ float g_xp1[(size_t)G4 * SBN];           // dir-r input proj [g][sb]
static __device__ float g_out0[(size_t)SBN * HD2];         // layer0 output [sb][512]
static __device__ float g_out1[(size_t)SBN * HD2];         // layer1 output [sb][512]
static __device__ float g_hB[2][2][NGRP][HH * 4];          // [buf][dir][grp][k*4+bi]
static __device__ float g_em[(size_t)SBN * LLAB];          // emissions [sb][9]
static __device__ float g_partial[BB];
static __device__ unsigned g_barcnt[16];
static __device__ unsigned g_bargen[16];

// ---------------- helpers ----------------
__device__ __forceinline__ float sigmf(float x) {
    return __fdividef(1.f, 1.f + __expf(-x));
}
__device__ __forceinline__ float tanhf_fast(float x) {
    x = fminf(12.f, fmaxf(-12.f, x));
    float e = __expf(-2.f * x);
    return __fdividef(1.f - e, 1.f + e);
}
__device__ __forceinline__ unsigned long long pack2(float lo, float hi) {
    unsigned long long r;
    asm("mov.b64 %0, {%1, %2};" : "=l"(r) : "f"(lo), "f"(hi));
    return r;
}
__device__ __forceinline__ void fma2(unsigned long long& d, unsigned long long a,
                                     unsigned long long b) {
    asm("fma.rn.f32x2 %0, %1, %2, %0;" : "+l"(d) : "l"(a), "l"(b));
}
__device__ __forceinline__ void add2(unsigned long long& d, unsigned long long a) {
    asm("add.rn.f32x2 %0, %0, %1;" : "+l"(d) : "l"(a));
}

// Per-group sense-reversing barrier (all NCPG CTAs of the group co-resident).
__device__ __forceinline__ void grid_barrier(int d, unsigned nb) {
    __threadfence();
    __syncthreads();
    if (threadIdx.x == 0) {
        unsigned gen = *((volatile unsigned*)&g_bargen[d]);
        if (atomicAdd(&g_barcnt[d], 1u) == nb - 1u) {
            g_barcnt[d] = 0u;
            __threadfence();
            atomicAdd(&g_bargen[d], 1u);
        } else {
            while (*((volatile unsigned*)&g_bargen[d]) == gen) { }
        }
        __threadfence();
    }
    __syncthreads();
}

// ---------------- kernel 1: C[m][n] = A[m][:K] . B[n][:K] + bias[m] ----------------
// (unchanged from the passing Round-10 kernel)
__global__ void gemm_nt2(const float* __restrict__ A0, const float* __restrict__ bias0,
                         float* __restrict__ C0,
                         const float* __restrict__ A1, const float* __restrict__ bias1,
                         float* __restrict__ C1,
                         const float* __restrict__ Bm, const int* __restrict__ ids,
                         int N, int K) {
    const float* A    = blockIdx.z ? A1 : A0;
    const float* bias = blockIdx.z ? bias1 : bias0;
    float*       C    = blockIdx.z ? C1 : C0;

    __shared__ __align__(16) float As[16][64];
    __shared__ __align__(16) float Bs[16][64];
    const int tid = threadIdx.x;
    const int tx = tid & 15, ty = tid >> 4;
    const int m0 = blockIdx.y * 64, n0 = blockIdx.x * 64;
    const int lr = tid >> 2;
    const int lk = (tid & 3) * 4;
    float acc[4][4] = {};
    const float* Ap = A + (size_t)(m0 + lr) * K + lk;
    int brow = n0 + lr;
    const float* Bp;
    if (ids) {
        int t = brow >> 5, b = brow & 31;
        int tok = ids[b * SS + t];
        Bp = Bm + (size_t)tok * K + lk;
    } else {
        Bp = Bm + (size_t)brow * K + lk;
    }

    float4 a4 = *(const float4*)(Ap);
    float4 b4 = *(const float4*)(Bp);

    for (int k0 = 0; k0 < K; k0 += 16) {
        As[lk + 0][lr] = a4.x; As[lk + 1][lr] = a4.y;
        As[lk + 2][lr] = a4.z; As[lk + 3][lr] = a4.w;
        Bs[lk + 0][lr] = b4.x; Bs[lk + 1][lr] = b4.y;
        Bs[lk + 2][lr] = b4.z; Bs[lk + 3][lr] = b4.w;
        __syncthreads();
        if (k0 + 16 < K) {
            a4 = *(const float4*)(Ap + k0 + 16);
            b4 = *(const float4*)(Bp + k0 + 16);
        }
#pragma unroll
        for (int kk = 0; kk < 16; ++kk) {
            float4 av = *(const float4*)&As[kk][ty * 4];
            float4 bv = *(const float4*)&Bs[kk][tx * 4];
            acc[0][0] = fmaf(av.x, bv.x, acc[0][0]);
            acc[0][1] = fmaf(av.x, bv.y, acc[0][1]);
            acc[0][2] = fmaf(av.x, bv.z, acc[0][2]);
            acc[0][3] = fmaf(av.x, bv.w, acc[0][3]);
            acc[1][0] = fmaf(av.y, bv.x, acc[1][0]);
            acc[1][1] = fmaf(av.y, bv.y, acc[1][1]);
            acc[1][2] = fmaf(av.y, bv.z, acc[1][2]);
            acc[1][3] = fmaf(av.y, bv.w, acc[1][3]);
            acc[2][0] = fmaf(av.z, bv.x, acc[2][0]);
            acc[2][1] = fmaf(av.z, bv.y, acc[2][1]);
            acc[2][2] = fmaf(av.z, bv.z, acc[2][2]);
            acc[2][3] = fmaf(av.z, bv.w, acc[2][3]);
            acc[3][0] = fmaf(av.w, bv.x, acc[3][0]);
            acc[3][1] = fmaf(av.w, bv.y, acc[3][1]);
            acc[3][2] = fmaf(av.w, bv.z, acc[3][2]);
            acc[3][3] = fmaf(av.w, bv.w, acc[3][3]);
        }
        __syncthreads();
    }
#pragma unroll
    for (int i = 0; i < 4; ++i) {
        int m = m0 + ty * 4 + i;
        float bb = bias[m];
        float4 o = make_float4(acc[i][0] + bb, acc[i][1] + bb,
                               acc[i][2] + bb, acc[i][3] + bb);
        *(float4*)&C[(size_t)m * N + n0 + tx * 4] = o;
    }
}

// ---------------- kernel 2: batch-grouped persistent BiLSTM layer ----------------
// Grid = 128 CTAs, 128 threads. blockIdx = dir*64 + grp*8 + hp.
// Group (dir,grp) = 8 CTAs handling batches grp*4..+3; CTA hp owns h-units
// hp*32..+31 (gate rows q*256 + hp*32 + j). Groups are fully independent:
// barrier scope is 8 CTAs; h exchange is 4 KB/step.
// Inner loop: thread = (ks = k-quarter 0..3, rq = row-quad 0..31); per iter
// 1 LDS.128 (4 w) + 1 LDS.128 (h quad, broadcast) + 8 fma.rn.f32x2 = 16 FMA.
// Dynamic smem (floats):
//   w   [256][128] @ 0      (128 KB, [k][lr])
//   h   [256][4]   @ 32768  (4 KB)
//   red u64[4][128][2] @ 33792 (8 KB)
//   g   [128][4]   @ 35840  (2 KB)
#define LSTM_SMEM_BYTES ((32768 + 1024 + 2048 + 512) * 4)
__global__ void lstm_layer(const float* __restrict__ xpf, const float* __restrict__ xpr,
                           const float* __restrict__ whhf, const float* __restrict__ whhr,
                           float* __restrict__ out) {
    extern __shared__ __align__(16) float sm[];
    float* sh_w = sm;                                            // [k*128 + lr]
    float* sh_h = sm + 32768;                                    // [k*4 + bi]
    unsigned long long* sh_red = (unsigned long long*)(sm + 33792); // [ks*128+lr][2]
    float* sh_g = sm + 35840;                                    // [lr*4 + bi]

    const int tid = threadIdx.x;
    const int dir = blockIdx.x >> 6;
    const int grp = (blockIdx.x >> 3) & 7;
    const int hp  = blockIdx.x & 7;
    const int bid = dir * 8 + grp;
    const float* xp  = dir ? xpr : xpf;
    const float* whh = dir ? whhr : whhf;

    // load weight slice once: 128 rows x 256 k, stored [k][lr]
    for (int i = tid; i < 8192; i += 128) {
        int lr0 = i >> 6, c4 = (i & 63) << 2;
        int q = lr0 >> 5, j = lr0 & 31;
        float4 v = *(const float4*)&whh[(size_t)(q * 256 + hp * 32 + j) * 256 + c4];
        sh_w[(c4 + 0) * 128 + lr0] = v.x;
        sh_w[(c4 + 1) * 128 + lr0] = v.y;
        sh_w[(c4 + 2) * 128 + lr0] = v.z;
        sh_w[(c4 + 3) * 128 + lr0] = v.w;
    }
    // zero partials (consumed unchanged at step 0 where h == 0)
    for (int i = tid; i < 1024; i += 128) sh_red[i] = 0ull;

    const int ks = tid >> 5;        // k quarter 0..3
    const int rq = tid & 31;        // row quad (rows rq*4..+3)
    const int lrr = tid;            // reduce-phase gate row 0..127
    const int qq = lrr >> 5, jj = lrr & 31;
    const float* xrow = xp + (size_t)(qq * 256 + hp * 32 + jj) * SBN;
    const int cj = tid >> 2, cb = tid & 3;   // cell-update: h-unit cj, batch cb
    float c_reg = 0.f;
    __syncthreads();

    int cur = 0;
    for (int step = 0; step < SS; ++step) {
        int t = dir ? (SS - 1 - step) : step;
        float4 xv = *(const float4*)&xrow[t * 32 + grp * 4];   // gates input proj

        if (step > 0) {
            // stage group h (4 KB) from L2 (written by peer CTAs)
            const float4* src = (const float4*)&g_hB[cur][dir][grp][0];
            float4* dst = (float4*)sh_h;
            dst[tid]       = __ldcg(&src[tid]);
            dst[tid + 128] = __ldcg(&src[tid + 128]);
            __syncthreads();

            unsigned long long a01_0 = 0, a23_0 = 0, a01_1 = 0, a23_1 = 0;
            unsigned long long a01_2 = 0, a23_2 = 0, a01_3 = 0, a23_3 = 0;
            const float4* wbase = (const float4*)sh_w + rq;        // + k*32
            const ulonglong2* hbase = (const ulonglong2*)sh_h;     // + k
#pragma unroll 8
            for (int kk = 0; kk < 64; ++kk) {
                int k = ks * 64 + kk;
                float4 wv = wbase[k * 32];
                ulonglong2 hv = hbase[k];
                unsigned long long w0 = pack2(wv.x, wv.x);
                unsigned long long w1 = pack2(wv.y, wv.y);
                unsigned long long w2 = pack2(wv.z, wv.z);
                unsigned long long w3 = pack2(wv.w, wv.w);
                fma2(a01_0, w0, hv.x); fma2(a23_0, w0, hv.y);
                fma2(a01_1, w1, hv.x); fma2(a23_1, w1, hv.y);
                fma2(a01_2, w2, hv.x); fma2(a23_2, w2, hv.y);
                fma2(a01_3, w3, hv.x); fma2(a23_3, w3, hv.y);
            }
            ulonglong2* R = (ulonglong2*)sh_red;
            R[ks * 128 + rq * 4 + 0] = make_ulonglong2(a01_0, a23_0);
            R[ks * 128 + rq * 4 + 1] = make_ulonglong2(a01_1, a23_1);
            R[ks * 128 + rq * 4 + 2] = make_ulonglong2(a01_2, a23_2);
            R[ks * 128 + rq * 4 + 3] = make_ulonglong2(a01_3, a23_3);
        }
        __syncthreads();

        // reduce the 4 k-quarters + input projection -> gates for row lrr
        {
            const ulonglong2* R = (const ulonglong2*)sh_red;
            ulonglong2 p0 = R[lrr], p1 = R[128 + lrr];
            ulonglong2 p2 = R[256 + lrr], p3 = R[384 + lrr];
            unsigned long long g01 = pack2(xv.x, xv.y);
            unsigned long long g23 = pack2(xv.z, xv.w);
            add2(g01, p0.x); add2(g23, p0.y);
            add2(g01, p1.x); add2(g23, p1.y);
            add2(g01, p2.x); add2(g23, p2.y);
            add2(g01, p3.x); add2(g23, p3.y);
            ((ulonglong2*)sh_g)[lrr] = make_ulonglong2(g01, g23);
        }
        __syncthreads();

        // cell update: thread -> (h-unit cj, batch cb); c lives in a register
        {
            float gi = sh_g[(0 * 32 + cj) * 4 + cb];
            float gf = sh_g[(1 * 32 + cj) * 4 + cb];
            float gg = sh_g[(2 * 32 + cj) * 4 + cb];
            float go = sh_g[(3 * 32 + cj) * 4 + cb];
            c_reg = sigmf(gf) * c_reg + sigmf(gi) * tanhf_fast(gg);
            float h = sigmf(go) * tanhf_fast(c_reg);
            __stcg(&g_hB[cur ^ 1][dir][grp][(hp * 32 + cj) * 4 + cb], h);
            out[((size_t)t * 32 + grp * 4 + cb) * HD2 + dir * 256 + hp * 32 + cj] = h;
        }
        grid_barrier(bid, NCPG);
        cur ^= 1;
    }
}

// ---------------- kernel 3: emissions ----------------
__global__ void emis_kernel(const float* __restrict__ x, const float* __restrict__ w,
                            const float* __restrict__ bo) {
    int row  = blockIdx.x * 8 + (threadIdx.x >> 5);
    int lane = threadIdx.x & 31;
    const float* xr = x + (size_t)row * HD2;
    float a[LLAB] = {};
#pragma unroll
    for (int i = 0; i < 16; ++i) {
        float xv = xr[i * 32 + lane];
#pragma unroll
        for (int l = 0; l < LLAB; ++l)
            a[l] = fmaf(xv, w[l * HD2 + i * 32 + lane], a[l]);
    }
#pragma unroll
    for (int off = 16; off > 0; off >>= 1) {
#pragma unroll
        for (int l = 0; l < LLAB; ++l)
            a[l] += __shfl_xor_sync(0xffffffffu, a[l], off);
    }
    if (lane < LLAB) g_em[(size_t)row * LLAB + lane] = a[lane] + bo[lane];
}

// ---------------- kernel 4: CRF (one block per batch, one warp) ----------------
__global__ void crf_kernel(const int* __restrict__ labels, const int* __restrict__ mask,
                           const float* __restrict__ start, const float* __restrict__ end_,
                           const float* __restrict__ trans) {
    __shared__ float em_s[SS][LLAB];
    __shared__ float tr_s[81], st_s[LLAB], en_s[LLAB];
    __shared__ int   tg_s[SS];
    __shared__ float mk_s[SS];
    __shared__ float sh_al[LLAB];
    const int b = blockIdx.x, tid = threadIdx.x;

    for (int i = tid; i < SS * LLAB; i += 32) {
        int t = i / LLAB, l = i - t * LLAB;
        em_s[t][l] = g_em[((size_t)t * 32 + b) * LLAB + l];
    }
    for (int i = tid; i < 81; i += 32) tr_s[i] = trans[i];
    if (tid < LLAB) { st_s[tid] = start[tid]; en_s[tid] = end_[tid]; }
    for (int i = tid; i < SS; i += 32) {
        tg_s[i] = labels[b * SS + i];
        mk_s[i] = (float)mask[b * SS + i];
    }
    __syncwarp();

    const int j = tid;
    float a = (j < LLAB) ? st_s[j] + em_s[0][j] : 0.f;
    for (int t = 1; t < SS; ++t) {
        if (j < LLAB) sh_al[j] = a;
        __syncwarp();
        if (j < LLAB) {
            float m = -1e30f;
#pragma unroll
            for (int i = 0; i < LLAB; ++i) m = fmaxf(m, sh_al[i] + tr_s[i * LLAB + j]);
            float s = 0.f;
#pragma unroll
            for (int i = 0; i < LLAB; ++i) s += __expf(sh_al[i] + tr_s[i * LLAB + j] - m);
            float nxt = m + __logf(s) + em_s[t][j];
            if (mk_s[t] > 0.f) a = nxt;
        }
        __syncwarp();
    }
    if (j < LLAB) sh_al[j] = a;
    __syncwarp();
    if (tid == 0) {
        float m = -1e30f;
#pragma unroll
        for (int i = 0; i < LLAB; ++i) m = fmaxf(m, sh_al[i] + en_s[i]);
        float s = 0.f;
#pragma unroll
        for (int i = 0; i < LLAB; ++i) s += __expf(sh_al[i] + en_s[i] - m);
        float den = m + __logf(s);
        int prev = tg_s[0];
        float sc = st_s[prev] + em_s[0][prev];
        for (int t = 1; t < SS; ++t) {
            int tt = tg_s[t];
            float mm = mk_s[t];
            sc += (tr_s[prev * LLAB + tt] + em_s[t][tt]) * mm;
            if (mm > 0.f) prev = tt;
        }
        sc += en_s[prev];
        g_partial[b] = den - sc;
    }
}

__global__ void final_sum(float* __restrict__ out) {
    float s = 0.f;
#pragma unroll
    for (int i = 0; i < BB; ++i) s += g_partial[i];
    out[0] = s;
}

// ---------------- launch ----------------
extern "C" void kernel_launch(void* const* d_in, const int* in_sizes, int n_in,
                              void* d_out, int out_size) {
    (void)in_sizes; (void)n_in; (void)out_size;
    const int*   ids    = (const int*)d_in[0];
    const int*   amask  = (const int*)d_in[1];
    const int*   labels = (const int*)d_in[2];
    const float* emb    = (const float*)d_in[3];
    const float* wih0f  = (const float*)d_in[4];
    const float* whh0f  = (const float*)d_in[5];
    const float* b0f    = (const float*)d_in[6];
    const float* wih0r  = (const float*)d_in[7];
    const float* whh0r  = (const float*)d_in[8];
    const float* b0r    = (const float*)d_in[9];
    const float* wih1f  = (const float*)d_in[10];
    const float* whh1f  = (const float*)d_in[11];
    const float* b1f    = (const float*)d_in[12];
    const float* wih1r  = (const float*)d_in[13];
    const float* whh1r  = (const float*)d_in[14];
    const float* b1r    = (const float*)d_in[15];
    const float* w_out  = (const float*)d_in[16];
    const float* b_out  = (const float*)d_in[17];
    const float* start_t = (const float*)d_in[18];
    const float* end_t   = (const float*)d_in[19];
    const float* trans   = (const float*)d_in[20];

    float* xp0; cudaGetSymbolAddress((void**)&xp0, g_xp0);
    float* xp1; cudaGetSymbolAddress((void**)&xp1, g_xp1);
    float* out0; cudaGetSymbolAddress((void**)&out0, g_out0);
    float* out1; cudaGetSymbolAddress((void**)&out1, g_out1);

    cudaFuncSetAttribute(lstm_layer, cudaFuncAttributeMaxDynamicSharedMemorySize,
                         LSTM_SMEM_BYTES);

    dim3 pgrid(SBN / 64, G4 / 64, 2), pblk(256);
    gemm_nt2<<<pgrid, pblk>>>(wih0f, b0f, xp0, wih0r, b0r, xp1, emb, ids, SBN, EE);

    lstm_layer<<<128, 128, LSTM_SMEM_BYTES>>>(xp0, xp1, whh0f, whh0r, out0);

    gemm_nt2<<<pgrid, pblk>>>(wih1f, b1f, xp0, wih1r, b1r, xp1, out0, nullptr, SBN, HD2);

    lstm_layer<<<128, 128, LSTM_SMEM_BYTES>>>(xp0, xp1, whh1f, whh1r, out1);

    emis_kernel<<<SBN / 8, 256>>>(out1, w_out, b_out);
    crf_kernel<<<BB, 32>>>(labels, amask, start_t, end_t, trans);
    final_sum<<<1, 1>>>((float*)d_out);
}